// round 1
// baseline (speedup 1.0000x reference)
#include <cuda_runtime.h>
#include <cuda_bf16.h>
#include <math.h>

// Problem constants (fixed by the dataset)
#define NN 100000
#define EE 1600000
#define DD 64
#define TAU 0.5f
#define ITERS 10

// Scratch (no cudaMalloc allowed)
__device__ float g_X[NN * DD];     // node features after each layer
__device__ float g_AX[NN * DD];    // SpMM result
__device__ float g_v[NN];          // power-iteration vector
__device__ float g_tmp[NN];        // SpMV result / shrunk vector
__device__ float g_norm;           // scalar norm accumulator

// ---------------------------------------------------------------------------
// Zero a float buffer (float4 grid-stride)
__global__ void zero_buf_kernel(float4* buf, int n4) {
    int i = blockIdx.x * blockDim.x + threadIdx.x;
    int stride = gridDim.x * blockDim.x;
    float4 z = make_float4(0.f, 0.f, 0.f, 0.f);
    for (; i < n4; i += stride) buf[i] = z;
}

// Zero vector + norm scalar
__global__ void zero_vec_kernel(float* tmp, int n) {
    int i = blockIdx.x * blockDim.x + threadIdx.x;
    if (i < n) tmp[i] = 0.f;
    if (i == 0) g_norm = 0.f;
}

// ---------------------------------------------------------------------------
// Dense-feature SpMM: AX[row[e]] += val[e] * X[col[e]]  (16 threads per edge)
__global__ void spmm_dense_kernel(const int* __restrict__ row,
                                  const int* __restrict__ col,
                                  const float* __restrict__ val,
                                  const float* __restrict__ X,
                                  float* __restrict__ AX, int E) {
    int idx = blockIdx.x * blockDim.x + threadIdx.x;
    int e = idx >> 4;
    int c = idx & 15;
    if (e >= E) return;
    int r  = __ldg(row + e);
    int cl = __ldg(col + e);
    float v = __ldg(val + e);
    float4 x = __ldg(((const float4*)(X + (size_t)cl * DD)) + c);
    float4 p = make_float4(v * x.x, v * x.y, v * x.z, v * x.w);
#if __CUDA_ARCH__ >= 900
    atomicAdd(((float4*)(AX + (size_t)r * DD)) + c, p);
#else
    float* dst = AX + (size_t)r * DD + c * 4;
    atomicAdd(dst + 0, p.x); atomicAdd(dst + 1, p.y);
    atomicAdd(dst + 2, p.z); atomicAdd(dst + 3, p.w);
#endif
}

// ---------------------------------------------------------------------------
// Fused residual linear: Xout[n,d] = Xin[n,d] + relu(sum_k AX[n,k]*W[d,k])
__global__ __launch_bounds__(128)
void fused_linear_kernel(const float* __restrict__ AX,
                         const float* __restrict__ Xin,
                         float* __restrict__ Xout,
                         const float* __restrict__ W) {
    __shared__ float4 Wsm[DD * (DD / 4)];  // 64x64 floats = 16KB
    for (int i = threadIdx.x; i < DD * DD / 4; i += blockDim.x)
        Wsm[i] = ((const float4*)W)[i];
    __syncthreads();

    int n = blockIdx.x * blockDim.x + threadIdx.x;
    if (n >= NN) return;

    float4 ax[16];
    const float4* axr = (const float4*)(AX + (size_t)n * DD);
#pragma unroll
    for (int i = 0; i < 16; i++) ax[i] = axr[i];

    const float4* xir = (const float4*)(Xin + (size_t)n * DD);
    float4* xo = (float4*)(Xout + (size_t)n * DD);

#pragma unroll
    for (int dg = 0; dg < 16; dg++) {
        float acc[4] = {0.f, 0.f, 0.f, 0.f};
#pragma unroll
        for (int j = 0; j < 4; j++) {
            int d = dg * 4 + j;
#pragma unroll
            for (int k4 = 0; k4 < 16; k4++) {
                float4 w = Wsm[d * 16 + k4];
                acc[j] += ax[k4].x * w.x + ax[k4].y * w.y +
                          ax[k4].z * w.z + ax[k4].w * w.w;
            }
        }
        float4 xi = xir[dg];
        float4 out;
        out.x = xi.x + fmaxf(acc[0], 0.f);
        out.y = xi.y + fmaxf(acc[1], 0.f);
        out.z = xi.z + fmaxf(acc[2], 0.f);
        out.w = xi.w + fmaxf(acc[3], 0.f);
        xo[dg] = out;
    }
}

// ---------------------------------------------------------------------------
// s[n] = dot(X[n,:], Ws)
__global__ void score_kernel(const float* __restrict__ X,
                             const float* __restrict__ Ws,
                             float* __restrict__ v) {
    int n = blockIdx.x * blockDim.x + threadIdx.x;
    if (n >= NN) return;
    const float4* xr = (const float4*)(X + (size_t)n * DD);
    const float4* wr = (const float4*)Ws;
    float acc = 0.f;
#pragma unroll
    for (int k4 = 0; k4 < 16; k4++) {
        float4 x = xr[k4];
        float4 w = __ldg(wr + k4);
        acc += x.x * w.x + x.y * w.y + x.z * w.z + x.w * w.w;
    }
    v[n] = acc;
}

// ---------------------------------------------------------------------------
// SpMV: tmp[row[e]] += val[e] * v[col[e]]
__global__ void spmv_kernel(const int* __restrict__ row,
                            const int* __restrict__ col,
                            const float* __restrict__ val,
                            const float* __restrict__ v,
                            float* __restrict__ tmp, int E) {
    int e = blockIdx.x * blockDim.x + threadIdx.x;
    if (e >= E) return;
    atomicAdd(tmp + __ldg(row + e), __ldg(val + e) * __ldg(v + __ldg(col + e)));
}

// shrink: y = x - tau*sign(x); accumulate sum(y*y) into g_norm
__global__ void shrink_norm_kernel(float* __restrict__ tmp, int n) {
    int i = blockIdx.x * blockDim.x + threadIdx.x;
    float y = 0.f;
    if (i < n) {
        float x = tmp[i];
        float s = (x > 0.f) ? 1.f : ((x < 0.f) ? -1.f : 0.f);
        y = x - TAU * s;
        tmp[i] = y;
    }
    float sq = y * y;
    // warp reduce
#pragma unroll
    for (int off = 16; off > 0; off >>= 1)
        sq += __shfl_down_sync(0xFFFFFFFFu, sq, off);
    __shared__ float warp_sums[8];
    int lane = threadIdx.x & 31, wid = threadIdx.x >> 5;
    if (lane == 0) warp_sums[wid] = sq;
    __syncthreads();
    if (wid == 0) {
        sq = (lane < (blockDim.x >> 5)) ? warp_sums[lane] : 0.f;
#pragma unroll
        for (int off = 4; off > 0; off >>= 1)
            sq += __shfl_down_sync(0xFFFFFFFFu, sq, off);
        if (lane == 0) atomicAdd(&g_norm, sq);
    }
}

// v_out = tmp / max(sqrt(norm), 1e-12)
__global__ void scale_kernel(const float* __restrict__ tmp,
                             float* __restrict__ vout, int n) {
    int i = blockIdx.x * blockDim.x + threadIdx.x;
    if (i >= n) return;
    float nrm = sqrtf(g_norm);
    float inv = 1.f / fmaxf(nrm, 1e-12f);
    vout[i] = tmp[i] * inv;
}

// ---------------------------------------------------------------------------
extern "C" void kernel_launch(void* const* d_in, const int* in_sizes, int n_in,
                              void* d_out, int out_size) {
    const int*   A_row = (const int*)d_in[0];
    const int*   A_col = (const int*)d_in[1];
    const float* A_val = (const float*)d_in[2];
    const int*   L_row = (const int*)d_in[3];
    const int*   L_col = (const int*)d_in[4];
    const float* L_val = (const float*)d_in[5];
    const float* embed = (const float*)d_in[6];
    const float* W1    = (const float*)d_in[7];
    const float* W2    = (const float*)d_in[8];
    const float* Ws    = (const float*)d_in[9];

    const int E = in_sizes[0];
    const int N = in_sizes[6] / DD;
    float* out = (float*)d_out;

    float *X, *AX, *v, *tmp;
    cudaGetSymbolAddress((void**)&X,   g_X);
    cudaGetSymbolAddress((void**)&AX,  g_AX);
    cudaGetSymbolAddress((void**)&v,   g_v);
    cudaGetSymbolAddress((void**)&tmp, g_tmp);

    const int TB = 256;
    int nblk_feat = (N * DD / 4 + TB - 1) / TB;   // zero AX
    int nblk_spmm = (E * 16 + TB - 1) / TB;
    int nblk_lin  = (N + 127) / 128;
    int nblk_node = (N + TB - 1) / TB;
    int nblk_edge = (E + TB - 1) / TB;

    // Layer 1: AX = A @ embed ; X = embed + relu(AX @ W1^T)
    zero_buf_kernel<<<nblk_feat, TB>>>((float4*)AX, N * DD / 4);
    spmm_dense_kernel<<<nblk_spmm, TB>>>(A_row, A_col, A_val, embed, AX, E);
    fused_linear_kernel<<<nblk_lin, 128>>>(AX, embed, X, W1);

    // Layer 2: AX = A @ X ; X = X + relu(AX @ W2^T)
    zero_buf_kernel<<<nblk_feat, TB>>>((float4*)AX, N * DD / 4);
    spmm_dense_kernel<<<nblk_spmm, TB>>>(A_row, A_col, A_val, X, AX, E);
    fused_linear_kernel<<<nblk_lin, 128>>>(AX, X, X, W2);

    // scores
    score_kernel<<<nblk_node, TB>>>(X, Ws, v);

    // power iterations
    for (int it = 0; it < ITERS; it++) {
        zero_vec_kernel<<<nblk_node, TB>>>(tmp, N);
        spmv_kernel<<<nblk_edge, TB>>>(L_row, L_col, L_val, v, tmp, E);
        shrink_norm_kernel<<<nblk_node, TB>>>(tmp, N);
        float* dst = (it == ITERS - 1) ? out : v;
        scale_kernel<<<nblk_node, TB>>>(tmp, dst, N);
    }
}

// round 2
// speedup vs baseline: 1.0157x; 1.0157x over previous
#include <cuda_runtime.h>
#include <math.h>

#define NN 100000
#define EE 1600000
#define DD 64
#define TAU 0.5f
#define ITERS 10
#define PBLOCKS 592
#define PTHREADS 256
#define NBLK_SCAN ((NN + 1 + 255) / 256)   // 391

// ---------------- scratch (no cudaMalloc allowed) ----------------
__device__ float g_X[NN * DD];
__device__ float g_AX[NN * DD];
__device__ float g_v[NN];
__device__ float g_tmp[NN];
__device__ float g_norms[ITERS];
__device__ int   g_row_start[NN + 1];
__device__ int   g_row_fill[NN];
__device__ int2  g_epack[EE];          // {col, val_bits} in CSR order
__device__ int   g_bsum[512];
__device__ unsigned g_count;           // barrier arrive counter
__device__ volatile unsigned g_sense_v;// barrier release sense

// ---------------------------------------------------------------------------
// CSR build for A
__global__ void zero_counts_kernel() {
    int i = blockIdx.x * blockDim.x + threadIdx.x;
    if (i <= NN) g_row_start[i] = 0;
}

__global__ void hist_kernel(const int* __restrict__ row, int E) {
    int e = blockIdx.x * blockDim.x + threadIdx.x;
    if (e < E) atomicAdd(&g_row_start[__ldg(row + e) + 1], 1);
}

// inclusive scan, per-256 block + block sums
__global__ void scanA_kernel(int n) {
    __shared__ int sm[256];
    int i = blockIdx.x * 256 + threadIdx.x;
    int x = (i < n) ? g_row_start[i] : 0;
    sm[threadIdx.x] = x;
    __syncthreads();
#pragma unroll
    for (int off = 1; off < 256; off <<= 1) {
        int t = (threadIdx.x >= off) ? sm[threadIdx.x - off] : 0;
        __syncthreads();
        sm[threadIdx.x] += t;
        __syncthreads();
    }
    if (i < n) g_row_start[i] = sm[threadIdx.x];
    if (threadIdx.x == 255) g_bsum[blockIdx.x] = sm[255];
}

__global__ void scanB_kernel(int nb) {
    __shared__ int sm[512];
    int x = (threadIdx.x < nb) ? g_bsum[threadIdx.x] : 0;
    sm[threadIdx.x] = x;
    __syncthreads();
#pragma unroll
    for (int off = 1; off < 512; off <<= 1) {
        int t = (threadIdx.x >= off) ? sm[threadIdx.x - off] : 0;
        __syncthreads();
        sm[threadIdx.x] += t;
        __syncthreads();
    }
    if (threadIdx.x < nb) g_bsum[threadIdx.x] = sm[threadIdx.x];
}

__global__ void scanC_kernel(int n) {
    int i = blockIdx.x * 256 + threadIdx.x;
    if (i >= n) return;
    int add = (blockIdx.x > 0) ? g_bsum[blockIdx.x - 1] : 0;
    int val = g_row_start[i] + add;
    g_row_start[i] = val;
    if (i < NN) g_row_fill[i] = val;   // row_start[r] == S[r]
}

__global__ void scatter_kernel(const int* __restrict__ row,
                               const int* __restrict__ col,
                               const float* __restrict__ val, int E) {
    int e = blockIdx.x * blockDim.x + threadIdx.x;
    if (e >= E) return;
    int r = __ldg(row + e);
    int pos = atomicAdd(&g_row_fill[r], 1);
    g_epack[pos] = make_int2(__ldg(col + e), __float_as_int(__ldg(val + e)));
}

// ---------------------------------------------------------------------------
// CSR SpMM: 16 lanes per row, register float4 accumulators, one write per row
__global__ __launch_bounds__(256)
void spmm_csr_kernel(const float* __restrict__ X, float* __restrict__ AX) {
    int t = blockIdx.x * blockDim.x + threadIdx.x;
    int r = t >> 4;
    int c = t & 15;
    if (r >= NN) return;
    int s = __ldg(&g_row_start[r]);
    int e = __ldg(&g_row_start[r + 1]);
    float4 acc = make_float4(0.f, 0.f, 0.f, 0.f);
    for (int i = s; i < e; i++) {
        int2 p = __ldg(&g_epack[i]);                 // broadcast within group
        float v = __int_as_float(p.y);
        float4 x = __ldg(((const float4*)(X + (size_t)p.x * DD)) + c);
        acc.x += v * x.x; acc.y += v * x.y;
        acc.z += v * x.z; acc.w += v * x.w;
    }
    ((float4*)(AX + (size_t)r * DD))[c] = acc;
}

// ---------------------------------------------------------------------------
// Xout[n,:] = Xin[n,:] + relu(AX[n,:] @ W^T)
__global__ __launch_bounds__(128)
void fused_linear_kernel(const float* __restrict__ AX,
                         const float* __restrict__ Xin,
                         float* __restrict__ Xout,
                         const float* __restrict__ W) {
    __shared__ float4 Wsm[DD * 16];
    for (int i = threadIdx.x; i < DD * 16; i += 128)
        Wsm[i] = ((const float4*)W)[i];
    __syncthreads();
    int n = blockIdx.x * 128 + threadIdx.x;
    if (n >= NN) return;

    float4 ax[16];
    const float4* axr = (const float4*)(AX + (size_t)n * DD);
#pragma unroll
    for (int i = 0; i < 16; i++) ax[i] = axr[i];
    const float4* xir = (const float4*)(Xin + (size_t)n * DD);
    float4* xo = (float4*)(Xout + (size_t)n * DD);

#pragma unroll
    for (int dg = 0; dg < 16; dg++) {
        float acc[4] = {0.f, 0.f, 0.f, 0.f};
#pragma unroll
        for (int j = 0; j < 4; j++) {
            int d = dg * 4 + j;
#pragma unroll
            for (int k4 = 0; k4 < 16; k4++) {
                float4 w = Wsm[d * 16 + k4];
                acc[j] += ax[k4].x * w.x + ax[k4].y * w.y +
                          ax[k4].z * w.z + ax[k4].w * w.w;
            }
        }
        float4 xi = xir[dg];
        float4 o;
        o.x = xi.x + fmaxf(acc[0], 0.f);
        o.y = xi.y + fmaxf(acc[1], 0.f);
        o.z = xi.z + fmaxf(acc[2], 0.f);
        o.w = xi.w + fmaxf(acc[3], 0.f);
        xo[dg] = o;
    }
}

// layer2 variant: also computes v[n] = dot(Xout[n,:], Ws)
__global__ __launch_bounds__(128)
void fused_linear2_kernel(const float* __restrict__ AX,
                          const float* __restrict__ Xin,
                          float* __restrict__ Xout,
                          const float* __restrict__ W,
                          const float* __restrict__ Ws,
                          float* __restrict__ vout) {
    __shared__ float4 Wsm[DD * 16];
    __shared__ float4 WsSm[16];
    for (int i = threadIdx.x; i < DD * 16; i += 128)
        Wsm[i] = ((const float4*)W)[i];
    if (threadIdx.x < 16) WsSm[threadIdx.x] = ((const float4*)Ws)[threadIdx.x];
    __syncthreads();
    int n = blockIdx.x * 128 + threadIdx.x;
    if (n >= NN) return;

    float4 ax[16];
    const float4* axr = (const float4*)(AX + (size_t)n * DD);
#pragma unroll
    for (int i = 0; i < 16; i++) ax[i] = axr[i];
    const float4* xir = (const float4*)(Xin + (size_t)n * DD);
    float4* xo = (float4*)(Xout + (size_t)n * DD);

    float vacc = 0.f;
#pragma unroll
    for (int dg = 0; dg < 16; dg++) {
        float acc[4] = {0.f, 0.f, 0.f, 0.f};
#pragma unroll
        for (int j = 0; j < 4; j++) {
            int d = dg * 4 + j;
#pragma unroll
            for (int k4 = 0; k4 < 16; k4++) {
                float4 w = Wsm[d * 16 + k4];
                acc[j] += ax[k4].x * w.x + ax[k4].y * w.y +
                          ax[k4].z * w.z + ax[k4].w * w.w;
            }
        }
        float4 xi = xir[dg];
        float4 o;
        o.x = xi.x + fmaxf(acc[0], 0.f);
        o.y = xi.y + fmaxf(acc[1], 0.f);
        o.z = xi.z + fmaxf(acc[2], 0.f);
        o.w = xi.w + fmaxf(acc[3], 0.f);
        xo[dg] = o;
        float4 ws = WsSm[dg];
        vacc += o.x * ws.x + o.y * ws.y + o.z * ws.z + o.w * ws.w;
    }
    vout[n] = vacc;
}

// ---------------------------------------------------------------------------
// Software grid barrier (all PBLOCKS are co-resident by construction)
__device__ __forceinline__ void grid_sync(unsigned* sense) {
    __syncthreads();
    if (threadIdx.x == 0) {
        unsigned s = *sense + 1;
        *sense = s;
        __threadfence();
        unsigned prev = atomicAdd(&g_count, 1u);
        if (prev == gridDim.x - 1) {
            g_count = 0;
            __threadfence();
            g_sense_v = s;
        } else {
            while (g_sense_v != s) __nanosleep(64);
            __threadfence();
        }
    }
    __syncthreads();
}

// All 10 power iterations in one launch. v/tmp cross-SM traffic via .cg
// (L2-coherent) ops; L edge data stays L1-resident across iterations.
__global__ __launch_bounds__(PTHREADS, 4)
void power_kernel(const int* __restrict__ Lrow, const int* __restrict__ Lcol,
                  const float* __restrict__ Lval, float* __restrict__ out,
                  int E) {
    __shared__ unsigned sense;
    __shared__ float wsum[PTHREADS / 32];
    const int gtid = blockIdx.x * PTHREADS + threadIdx.x;
    const int gstride = gridDim.x * PTHREADS;
    if (threadIdx.x == 0) sense = g_sense_v;

    // phase 0: zero tmp + norms
    for (int i = gtid; i < NN; i += gstride) __stcg(&g_tmp[i], 0.f);
    if (gtid < ITERS) __stcg(&g_norms[gtid], 0.f);
    grid_sync(&sense);

    const int i0 = gtid, i1 = gtid + gstride;

    for (int it = 0; it < ITERS; it++) {
        // --- SpMV: tmp[row] += val * v[col] ---
        for (int e = gtid; e < E; e += gstride) {
            float vv = __ldcg(&g_v[__ldg(Lcol + e)]);
            atomicAdd(&g_tmp[__ldg(Lrow + e)], __ldg(Lval + e) * vv);
        }
        grid_sync(&sense);

        // --- shrink + norm (y kept in registers) ---
        float y0 = 0.f, y1 = 0.f, local = 0.f;
        if (i0 < NN) {
            float x = __ldcg(&g_tmp[i0]);
            float sg = (x > 0.f) ? 1.f : ((x < 0.f) ? -1.f : 0.f);
            y0 = x - TAU * sg; local += y0 * y0;
        }
        if (i1 < NN) {
            float x = __ldcg(&g_tmp[i1]);
            float sg = (x > 0.f) ? 1.f : ((x < 0.f) ? -1.f : 0.f);
            y1 = x - TAU * sg; local += y1 * y1;
        }
#pragma unroll
        for (int off = 16; off > 0; off >>= 1)
            local += __shfl_down_sync(0xFFFFFFFFu, local, off);
        int lane = threadIdx.x & 31, wid = threadIdx.x >> 5;
        if (lane == 0) wsum[wid] = local;
        __syncthreads();
        if (wid == 0) {
            local = (lane < (PTHREADS >> 5)) ? wsum[lane] : 0.f;
#pragma unroll
            for (int off = 4; off > 0; off >>= 1)
                local += __shfl_down_sync(0xFFFFFFFFu, local, off);
            if (lane == 0) atomicAdd(&g_norms[it], local);
        }
        grid_sync(&sense);

        // --- scale (and reset tmp for next iteration) ---
        float nrm = sqrtf(__ldcg(&g_norms[it]));
        float inv = 1.f / fmaxf(nrm, 1e-12f);
        float* dst = (it == ITERS - 1) ? out : g_v;
        if (i0 < NN) { __stcg(&dst[i0], y0 * inv); __stcg(&g_tmp[i0], 0.f); }
        if (i1 < NN) { __stcg(&dst[i1], y1 * inv); __stcg(&g_tmp[i1], 0.f); }
        grid_sync(&sense);
    }
}

// ---------------------------------------------------------------------------
extern "C" void kernel_launch(void* const* d_in, const int* in_sizes, int n_in,
                              void* d_out, int out_size) {
    const int*   A_row = (const int*)d_in[0];
    const int*   A_col = (const int*)d_in[1];
    const float* A_val = (const float*)d_in[2];
    const int*   L_row = (const int*)d_in[3];
    const int*   L_col = (const int*)d_in[4];
    const float* L_val = (const float*)d_in[5];
    const float* embed = (const float*)d_in[6];
    const float* W1    = (const float*)d_in[7];
    const float* W2    = (const float*)d_in[8];
    const float* Ws    = (const float*)d_in[9];

    const int E = in_sizes[0];
    float* out = (float*)d_out;

    float *X, *AX, *v;
    cudaGetSymbolAddress((void**)&X,  g_X);
    cudaGetSymbolAddress((void**)&AX, g_AX);
    cudaGetSymbolAddress((void**)&v,  g_v);

    const int TB = 256;
    int nblk_edge = (E + TB - 1) / TB;
    int nblk_row  = (NN * 16 + TB - 1) / TB;      // 16 lanes per row
    int nblk_lin  = (NN + 127) / 128;

    // --- CSR build for A ---
    zero_counts_kernel<<<(NN + 1 + TB - 1) / TB, TB>>>();
    hist_kernel<<<nblk_edge, TB>>>(A_row, E);
    scanA_kernel<<<NBLK_SCAN, 256>>>(NN + 1);
    scanB_kernel<<<1, 512>>>(NBLK_SCAN);
    scanC_kernel<<<NBLK_SCAN, 256>>>(NN + 1);
    scatter_kernel<<<nblk_edge, TB>>>(A_row, A_col, A_val, E);

    // --- 2 GNN layers ---
    spmm_csr_kernel<<<nblk_row, TB>>>(embed, AX);
    fused_linear_kernel<<<nblk_lin, 128>>>(AX, embed, X, W1);
    spmm_csr_kernel<<<nblk_row, TB>>>(X, AX);
    fused_linear2_kernel<<<nblk_lin, 128>>>(AX, X, X, W2, Ws, v);

    // --- power iterations (single persistent kernel) ---
    power_kernel<<<PBLOCKS, PTHREADS>>>(L_row, L_col, L_val, out, E);
}